// round 16
// baseline (speedup 1.0000x reference)
#include <cuda_runtime.h>
#include <cuda_bf16.h>
#include <math.h>
#include <stdint.h>

#define N_PTS 131072
#define C 128
#define KNUM 27
#define M_MAP 65536
#define EPS 1e-5f

#define BT 128            // map rows per CTA tile
#define KC 32             // k-elems per chunk
#define NCHUNK (C / KC)   // 4
#define PB 80             // smem row pitch in BYTES (40 bf16) — LDSM conflict-free
#define ARR_SZ (BT * PB)  // 10240 B per operand array
#define A_STAGE (2 * ARR_SZ)    // Ahi+Alo = 20480 B
#define B_STAGE (2 * ARR_SZ)    // Bhi+Blo = 20480 B
#define BREG (3 * A_STAGE)      // B region starts after 3 A stages = 61440
#define DYN_SMEM (3 * A_STAGE + 2 * B_STAGE)   // 102400 B
#define WCHUNK_B ARR_SZ         // one weight chunk image = 10240 B
#define WLAYER_B ((size_t)KNUM * NCHUNK * WCHUNK_B)   // per-layer weight image bytes

// ---- scratch (static device allocations; allowed) ----
__device__ __align__(16) float         g_acc[(size_t)N_PTS * C];
__device__ __align__(16) __nv_bfloat16 g_xhi[(size_t)N_PTS * C];
__device__ __align__(16) __nv_bfloat16 g_xlo[(size_t)N_PTS * C];
__device__ __align__(16) __nv_bfloat16 g_yhi[(size_t)N_PTS * C];
__device__ __align__(16) __nv_bfloat16 g_ylo[(size_t)N_PTS * C];
// weight smem-images for BOTH layers: [layer][k][chunk][row][40 bf16 @80B pitch]
__device__ __align__(16) __nv_bfloat16 g_wthi[2 * (size_t)KNUM * NCHUNK * BT * (PB / 2)];
__device__ __align__(16) __nv_bfloat16 g_wtlo[2 * (size_t)KNUM * NCHUNK * BT * (PB / 2)];
__device__ __align__(16) float g_sum[C];
__device__ __align__(16) float g_sq[C];

// ---------------------------------------------------------------------------
// helpers
// ---------------------------------------------------------------------------
__device__ __forceinline__ uint32_t smem_u32(const void* p)
{
    uint32_t a;
    asm("{ .reg .u64 t; cvta.to.shared.u64 t, %1; cvt.u32.u64 %0, t; }"
        : "=r"(a) : "l"(p));
    return a;
}

__device__ __forceinline__ void split_bf16(float v, __nv_bfloat16& h, __nv_bfloat16& l)
{
    h = __float2bfloat16_rn(v);
    l = __float2bfloat16_rn(v - __bfloat162float(h));
}

__device__ __forceinline__ void mma16816(float* c, const unsigned* a,
                                         unsigned b0, unsigned b1)
{
    asm volatile(
        "mma.sync.aligned.m16n8k16.row.col.f32.bf16.bf16.f32 "
        "{%0,%1,%2,%3}, {%4,%5,%6,%7}, {%8,%9}, {%0,%1,%2,%3};"
        : "+f"(c[0]), "+f"(c[1]), "+f"(c[2]), "+f"(c[3])
        : "r"(a[0]), "r"(a[1]), "r"(a[2]), "r"(a[3]), "r"(b0), "r"(b1));
}

__device__ __forceinline__ void ldsm_x4(unsigned* r, uint32_t addr)
{
    asm volatile("ldmatrix.sync.aligned.m8n8.x4.shared.b16 {%0,%1,%2,%3}, [%4];"
                 : "=r"(r[0]), "=r"(r[1]), "=r"(r[2]), "=r"(r[3]) : "r"(addr));
}

#define CP_ASYNC16(dst, src) \
    asm volatile("cp.async.cg.shared.global [%0], [%1], 16;" :: "r"(dst), "l"(src))
#define CP_COMMIT() asm volatile("cp.async.commit_group;" ::: "memory")

__device__ __forceinline__ void bulk_copy(uint32_t dst, const void* src,
                                          uint32_t bytes, uint32_t mbar)
{
    asm volatile(
        "cp.async.bulk.shared::cta.global.mbarrier::complete_tx::bytes "
        "[%0], [%1], %2, [%3];"
        :: "r"(dst), "l"(src), "r"(bytes), "r"(mbar) : "memory");
}

__device__ __forceinline__ void mbar_expect_tx(uint32_t mbar, uint32_t bytes)
{
    asm volatile("mbarrier.arrive.expect_tx.shared.b64 _, [%0], %1;"
                 :: "r"(mbar), "r"(bytes) : "memory");
}

__device__ __forceinline__ void mbar_wait(uint32_t mbar, uint32_t parity)
{
    uint32_t done;
    asm volatile(
        "{\n\t.reg .pred p;\n\t"
        "mbarrier.try_wait.parity.acquire.cta.shared::cta.b64 p, [%1], %2;\n\t"
        "selp.b32 %0, 1, 0, p;\n\t}"
        : "=r"(done) : "r"(mbar), "r"(parity) : "memory");
    if (!done) {
        asm volatile(
            "{\n\t.reg .pred P1;\n\t"
            "WL_%=:\n\t"
            "mbarrier.try_wait.parity.acquire.cta.shared::cta.b64 P1, [%0], %1, 0x989680;\n\t"
            "@P1 bra.uni WD_%=;\n\t"
            "bra.uni WL_%=;\n\t"
            "WD_%=:\n\t}"
            :: "r"(mbar), "r"(parity) : "memory");
    }
}

__device__ __forceinline__ float elu_f(float x)
{
    return x > 0.0f ? x : expm1f(x);
}

// ---------------------------------------------------------------------------
// Prepack kernels
// ---------------------------------------------------------------------------
__global__ __launch_bounds__(256)
void prepack_x_kernel(const float* __restrict__ src,
                      __nv_bfloat16* __restrict__ hi,
                      __nv_bfloat16* __restrict__ lo,
                      float* __restrict__ acc_zero)
{
    size_t i = (size_t)blockIdx.x * 256 + threadIdx.x;
    float4 v = ((const float4*)src)[i];
    __nv_bfloat16 h0, h1, h2, h3, l0, l1, l2, l3;
    split_bf16(v.x, h0, l0); split_bf16(v.y, h1, l1);
    split_bf16(v.z, h2, l2); split_bf16(v.w, h3, l3);
    ((__nv_bfloat162*)hi)[i * 2 + 0] = __nv_bfloat162(h0, h1);
    ((__nv_bfloat162*)hi)[i * 2 + 1] = __nv_bfloat162(h2, h3);
    ((__nv_bfloat162*)lo)[i * 2 + 0] = __nv_bfloat162(l0, l1);
    ((__nv_bfloat162*)lo)[i * 2 + 1] = __nv_bfloat162(l2, l3);
    ((float4*)acc_zero)[i] = make_float4(0.f, 0.f, 0.f, 0.f);   // layer-1 acc zero
}

// Both layers in one launch: blocks 0..26 pack W1, 27..53 pack W2.
__global__ __launch_bounds__(256)
void prepack_w_kernel(const float* __restrict__ W1,
                      const float* __restrict__ W2)
{
    int b     = blockIdx.x;
    int layer = b >= KNUM ? 1 : 0;
    int k     = b - layer * KNUM;
    const float* Wk = (layer ? W2 : W1) + (size_t)k * C * C;
    __nv_bfloat16* oh = g_wthi + (size_t)layer * KNUM * NCHUNK * BT * (PB / 2);
    __nv_bfloat16* ol = g_wtlo + (size_t)layer * KNUM * NCHUNK * BT * (PB / 2);
    for (int idx = threadIdx.x; idx < C * C; idx += 256) {
        int n   = idx & (C - 1);
        int cin = idx >> 7;
        float v = Wk[(size_t)cin * C + n];
        __nv_bfloat16 h, l;
        split_bf16(v, h, l);
        int ch  = cin >> 5;
        int col = cin & 31;
        size_t off = ((size_t)(k * NCHUNK + ch) * BT + n) * (PB / 2) + col;
        oh[off] = h;
        ol[off] = l;
    }
}

// ---------------------------------------------------------------------------
// Sparse conv: mma.sync + ldmatrix; A via 3-stage cp.async, B via 2-stage bulk.
// CTA = 128 map rows x 128 out channels; 8 warps, warp tile 32M x 64N.
// ONE barrier per chunk. CTA(0,0) zeroes BN stats for the upcoming bn_stats.
// ---------------------------------------------------------------------------
__global__ __launch_bounds__(256, 2)
void spconv_mma_kernel(const __nv_bfloat16* __restrict__ xhi,
                       const __nv_bfloat16* __restrict__ xlo,
                       const __nv_bfloat16* __restrict__ wt_hi,
                       const __nv_bfloat16* __restrict__ wt_lo,
                       const int* __restrict__ map_in,
                       const int* __restrict__ map_out,
                       float* __restrict__ acc_out)
{
    extern __shared__ __align__(16) char dynsmem[];
    __shared__ int rowidx[BT];
    __shared__ int outidx[BT];
    __shared__ __align__(8) uint64_t s_mbar[2];

    const int k    = blockIdx.y;
    const int m0   = blockIdx.x * BT;
    const int tid  = threadIdx.x;
    const int warp = tid >> 5;
    const int lane = tid & 31;
    const int wm   = warp & 3;            // M warp: 32 rows
    const int wn   = warp >> 2;           // N warp: 64 cols

    if (blockIdx.x == 0 && blockIdx.y == 0 && tid < C) {
        g_sum[tid] = 0.0f;
        g_sq[tid]  = 0.0f;
    }

    const int* mi = map_in  + (size_t)k * M_MAP + m0;
    const int* mo = map_out + (size_t)k * M_MAP + m0;
    const char* wbh = (const char*)wt_hi + (size_t)k * NCHUNK * WCHUNK_B;
    const char* wbl = (const char*)wt_lo + (size_t)k * NCHUNK * WCHUNK_B;

    const uint32_t sbase = smem_u32(dynsmem);
    const uint32_t mb0   = smem_u32(&s_mbar[0]);
    const uint32_t mb1   = smem_u32(&s_mbar[1]);

    if (tid < BT) {
        rowidx[tid] = mi[tid];
        outidx[tid] = mo[tid];
    }
    if (tid == 0) {
        asm volatile("mbarrier.init.shared.b64 [%0], 1;" :: "r"(mb0) : "memory");
        asm volatile("mbarrier.init.shared.b64 [%0], 1;" :: "r"(mb1) : "memory");
        asm volatile("fence.proxy.async.shared::cta;" ::: "memory");
    }
    __syncthreads();

    // --- per-thread cp.async source/dest for A (4 transfers per chunk) ---
    const __nv_bfloat16* srcs[4];
    uint32_t doffs[4];
    #pragma unroll
    for (int it = 0; it < 4; it++) {
        int idx = tid + it * 256;          // 0..1023
        int a   = idx >> 9;                // 0: hi, 1: lo
        int rem = idx & 511;
        int row = rem >> 2;
        int q   = rem & 3;
        const __nv_bfloat16* s = (a == 0 ? xhi : xlo) + (size_t)rowidx[row] * C;
        srcs[it]  = s + q * 8;
        doffs[it] = (uint32_t)(a * ARR_SZ + row * PB + q * 16);
    }

    // --- ldmatrix per-thread offsets (within a stage) ---
    const int mat = lane >> 3;
    const int mi8 = lane & 7;
    const uint32_t aRow  = (uint32_t)(wm * 32 + (mat & 1) * 8 + mi8);
    const uint32_t aColB = (uint32_t)((mat >> 1) * 8) * 2;
    uint32_t aOff[2];
    aOff[0] = aRow * PB + aColB;
    aOff[1] = (aRow + 16) * PB + aColB;
    const uint32_t bRow  = (uint32_t)(wn * 64 + (mat >> 1) * 8 + mi8);
    const uint32_t bColB = (uint32_t)((mat & 1) * 8) * 2;
    uint32_t bOff[4];
    #pragma unroll
    for (int p = 0; p < 4; p++)
        bOff[p] = (bRow + p * 16) * PB + bColB;

    float acc[2][8][4];
    #pragma unroll
    for (int i = 0; i < 2; i++)
        #pragma unroll
        for (int j = 0; j < 8; j++)
            #pragma unroll
            for (int t = 0; t < 4; t++) acc[i][j][t] = 0.0f;

    // ---- preload: A chunks 0,1 (stages 0,1) and B chunk 0 (stage 0) ----
    #pragma unroll
    for (int pre = 0; pre < 2; pre++) {
        const uint32_t st = (uint32_t)(pre * A_STAGE);
        const int coff = pre * KC;
        #pragma unroll
        for (int it = 0; it < 4; it++)
            CP_ASYNC16(sbase + st + doffs[it], srcs[it] + coff);
        CP_COMMIT();
    }
    if (tid == 0) {
        mbar_expect_tx(mb0, 2 * WCHUNK_B);
        bulk_copy(sbase + BREG, wbh, WCHUNK_B, mb0);
        bulk_copy(sbase + BREG + ARR_SZ, wbl, WCHUNK_B, mb0);
    }

    #pragma unroll
    for (int ch = 0; ch < NCHUNK; ch++) {
        // ---- wait for chunk ch (A groups FIFO; B via mbarrier) ----
        if (ch < NCHUNK - 1) asm volatile("cp.async.wait_group 1;" ::: "memory");
        else                 asm volatile("cp.async.wait_group 0;" ::: "memory");
        mbar_wait((ch & 1) ? mb1 : mb0, (uint32_t)((ch >> 1) & 1));
        __syncthreads();   // ONLY barrier this chunk

        // ---- issue next-chunk copies (safe: stage readers all past barrier) ----
        if (ch + 2 < NCHUNK) {
            const uint32_t st = (uint32_t)(((ch + 2) % 3) * A_STAGE);
            const int coff = (ch + 2) * KC;
            #pragma unroll
            for (int it = 0; it < 4; it++)
                CP_ASYNC16(sbase + st + doffs[it], srcs[it] + coff);
            CP_COMMIT();
        }
        if (ch + 1 < NCHUNK && tid == 0) {
            const uint32_t nmb = ((ch + 1) & 1) ? mb1 : mb0;
            const uint32_t dst = sbase + BREG + (uint32_t)(((ch + 1) & 1) * B_STAGE);
            mbar_expect_tx(nmb, 2 * WCHUNK_B);
            bulk_copy(dst, wbh + (size_t)(ch + 1) * WCHUNK_B, WCHUNK_B, nmb);
            bulk_copy(dst + ARR_SZ, wbl + (size_t)(ch + 1) * WCHUNK_B, WCHUNK_B, nmb);
        }

        const uint32_t stA = sbase + (uint32_t)((ch % 3) * A_STAGE);
        const uint32_t stB = sbase + BREG + (uint32_t)((ch % 2) * B_STAGE);

        #pragma unroll
        for (int ks = 0; ks < KC / 16; ks++) {
            const uint32_t kb = (uint32_t)(ks * 32);
            unsigned ah[2][4], al[2][4];
            ldsm_x4(ah[0], stA + aOff[0] + kb);
            ldsm_x4(ah[1], stA + aOff[1] + kb);
            ldsm_x4(al[0], stA + ARR_SZ + aOff[0] + kb);
            ldsm_x4(al[1], stA + ARR_SZ + aOff[1] + kb);
            #pragma unroll
            for (int p = 0; p < 4; p++) {
                unsigned bh[4], bl[4];
                ldsm_x4(bh, stB + bOff[p] + kb);
                ldsm_x4(bl, stB + ARR_SZ + bOff[p] + kb);
                #pragma unroll
                for (int ns = 0; ns < 2; ns++) {
                    const int nb = p * 2 + ns;
                    #pragma unroll
                    for (int mb = 0; mb < 2; mb++) {
                        mma16816(acc[mb][nb], ah[mb], bh[ns * 2], bh[ns * 2 + 1]);
                        mma16816(acc[mb][nb], ah[mb], bl[ns * 2], bl[ns * 2 + 1]);
                        mma16816(acc[mb][nb], al[mb], bh[ns * 2], bh[ns * 2 + 1]);
                    }
                }
            }
        }
    }

    // ---- epilogue: shfl-swap fragments into 4-col runs, scatter v4 reds ----
    {
        const int g    = lane >> 2;
        const int tig  = lane & 3;
        const int oddp = tig & 1;
        #pragma unroll
        for (int mb = 0; mb < 2; mb++) {
            const int r    = wm * 32 + mb * 16 + g + oddp * 8;
            const int orow = outidx[r];
            float* dst = acc_out + (size_t)orow * C + wn * 64 + (tig >> 1) * 4;
            #pragma unroll
            for (int nb = 0; nb < 8; nb++) {
                float s0 = oddp ? acc[mb][nb][0] : acc[mb][nb][2];
                float s1 = oddp ? acc[mb][nb][1] : acc[mb][nb][3];
                float r0 = __shfl_xor_sync(0xFFFFFFFFu, s0, 1);
                float r1 = __shfl_xor_sync(0xFFFFFFFFu, s1, 1);
                float v0 = oddp ? r0 : acc[mb][nb][0];
                float v1 = oddp ? r1 : acc[mb][nb][1];
                float v2 = oddp ? acc[mb][nb][2] : r0;
                float v3 = oddp ? acc[mb][nb][3] : r1;
                asm volatile("red.global.v4.f32.add [%0], {%1, %2, %3, %4};"
                             :: "l"(dst + nb * 8), "f"(v0), "f"(v1), "f"(v2), "f"(v3)
                             : "memory");
            }
        }
    }
}

// ---------------------------------------------------------------------------
// BN stats (4-way unrolled for MLP)
// ---------------------------------------------------------------------------
__global__ __launch_bounds__(256)
void bn_stats_kernel(const float* __restrict__ a)
{
    __shared__ float4 ss[256];
    __shared__ float4 qq[256];
    const int tid = threadIdx.x;
    const int c4  = tid & 31;
    const int ro  = tid >> 5;

    float4 s = make_float4(0.f, 0.f, 0.f, 0.f);
    float4 p = make_float4(0.f, 0.f, 0.f, 0.f);
    for (int r = blockIdx.x * 32 + ro; r < N_PTS; r += gridDim.x * 32) {
        float4 v0 = ((const float4*)a)[(size_t)r * 32 + c4];
        float4 v1 = ((const float4*)a)[(size_t)(r + 8) * 32 + c4];
        float4 v2 = ((const float4*)a)[(size_t)(r + 16) * 32 + c4];
        float4 v3 = ((const float4*)a)[(size_t)(r + 24) * 32 + c4];
        s.x += (v0.x + v1.x) + (v2.x + v3.x);
        s.y += (v0.y + v1.y) + (v2.y + v3.y);
        s.z += (v0.z + v1.z) + (v2.z + v3.z);
        s.w += (v0.w + v1.w) + (v2.w + v3.w);
        p.x += (v0.x * v0.x + v1.x * v1.x) + (v2.x * v2.x + v3.x * v3.x);
        p.y += (v0.y * v0.y + v1.y * v1.y) + (v2.y * v2.y + v3.y * v3.y);
        p.z += (v0.z * v0.z + v1.z * v1.z) + (v2.z * v2.z + v3.z * v3.z);
        p.w += (v0.w * v0.w + v1.w * v1.w) + (v2.w * v2.w + v3.w * v3.w);
    }
    ss[tid] = s;
    qq[tid] = p;
    __syncthreads();
    if (tid < 32) {
        float4 S = ss[tid], Q = qq[tid];
        #pragma unroll
        for (int j = 1; j < 8; j++) {
            float4 s2 = ss[tid + j * 32], q2 = qq[tid + j * 32];
            S.x += s2.x; S.y += s2.y; S.z += s2.z; S.w += s2.w;
            Q.x += q2.x; Q.y += q2.y; Q.z += q2.z; Q.w += q2.w;
        }
        atomicAdd(&g_sum[tid * 4 + 0], S.x);
        atomicAdd(&g_sum[tid * 4 + 1], S.y);
        atomicAdd(&g_sum[tid * 4 + 2], S.z);
        atomicAdd(&g_sum[tid * 4 + 3], S.w);
        atomicAdd(&g_sq[tid * 4 + 0], Q.x);
        atomicAdd(&g_sq[tid * 4 + 1], Q.y);
        atomicAdd(&g_sq[tid * 4 + 2], Q.z);
        atomicAdd(&g_sq[tid * 4 + 3], Q.w);
    }
}

// ---------------------------------------------------------------------------
// Apply kernels: finalize folded in, 8 float4s per thread (grid = elem4/2048)
// ---------------------------------------------------------------------------
__global__ __launch_bounds__(256)
void apply_bn_elu_split_kernel(float* __restrict__ a,
                               const float* __restrict__ gamma,
                               const float* __restrict__ beta,
                               __nv_bfloat16* __restrict__ yh,
                               __nv_bfloat16* __restrict__ yl)
{
    __shared__ float s_scale[C];
    __shared__ float s_shift[C];
    const int tid = threadIdx.x;
    if (tid < C) {
        float m  = g_sum[tid] * (1.0f / N_PTS);
        float v  = g_sq[tid] * (1.0f / N_PTS) - m * m;
        float is = rsqrtf(v + EPS);
        float sc = is * gamma[tid];
        s_scale[tid] = sc;
        s_shift[tid] = beta[tid] - m * sc;
    }
    __syncthreads();
    const int c4 = tid & 31;
    float4 sc = ((const float4*)s_scale)[c4];
    float4 sh = ((const float4*)s_shift)[c4];
    #pragma unroll
    for (int it = 0; it < 8; it++) {
        size_t idx = (size_t)blockIdx.x * 2048 + it * 256 + tid;
        float4 v = ((const float4*)a)[idx];
        ((float4*)a)[idx] = make_float4(0.f, 0.f, 0.f, 0.f);   // zero acc for L2
        float4 r;
        r.x = elu_f(fmaf(v.x, sc.x, sh.x));
        r.y = elu_f(fmaf(v.y, sc.y, sh.y));
        r.z = elu_f(fmaf(v.z, sc.z, sh.z));
        r.w = elu_f(fmaf(v.w, sc.w, sh.w));
        __nv_bfloat16 h0, h1, h2, h3, l0, l1, l2, l3;
        split_bf16(r.x, h0, l0); split_bf16(r.y, h1, l1);
        split_bf16(r.z, h2, l2); split_bf16(r.w, h3, l3);
        ((__nv_bfloat162*)yh)[idx * 2 + 0] = __nv_bfloat162(h0, h1);
        ((__nv_bfloat162*)yh)[idx * 2 + 1] = __nv_bfloat162(h2, h3);
        ((__nv_bfloat162*)yl)[idx * 2 + 0] = __nv_bfloat162(l0, l1);
        ((__nv_bfloat162*)yl)[idx * 2 + 1] = __nv_bfloat162(l2, l3);
    }
}

__global__ __launch_bounds__(256)
void apply_bn_res_elu_kernel(const float* __restrict__ a,
                             const float* __restrict__ gamma,
                             const float* __restrict__ beta,
                             const float* __restrict__ resid,
                             float* __restrict__ o)
{
    __shared__ float s_scale[C];
    __shared__ float s_shift[C];
    const int tid = threadIdx.x;
    if (tid < C) {
        float m  = g_sum[tid] * (1.0f / N_PTS);
        float v  = g_sq[tid] * (1.0f / N_PTS) - m * m;
        float is = rsqrtf(v + EPS);
        float sc = is * gamma[tid];
        s_scale[tid] = sc;
        s_shift[tid] = beta[tid] - m * sc;
    }
    __syncthreads();
    const int c4 = tid & 31;
    float4 sc = ((const float4*)s_scale)[c4];
    float4 sh = ((const float4*)s_shift)[c4];
    #pragma unroll
    for (int it = 0; it < 8; it++) {
        size_t idx = (size_t)blockIdx.x * 2048 + it * 256 + tid;
        float4 v  = ((const float4*)a)[idx];
        float4 rs = ((const float4*)resid)[idx];
        float4 r;
        r.x = elu_f(fmaf(v.x, sc.x, sh.x) + rs.x);
        r.y = elu_f(fmaf(v.y, sc.y, sh.y) + rs.y);
        r.z = elu_f(fmaf(v.z, sc.z, sh.z) + rs.z);
        r.w = elu_f(fmaf(v.w, sc.w, sh.w) + rs.w);
        ((float4*)o)[idx] = r;
    }
}

// ---------------------------------------------------------------------------
// Launch
// ---------------------------------------------------------------------------
extern "C" void kernel_launch(void* const* d_in, const int* in_sizes, int n_in,
                              void* d_out, int out_size)
{
    const float* x       = (const float*)d_in[0];
    const float* W1      = (const float*)d_in[1];
    const float* gamma1  = (const float*)d_in[2];
    const float* beta1   = (const float*)d_in[3];
    const float* W2      = (const float*)d_in[4];
    const float* gamma2  = (const float*)d_in[5];
    const float* beta2   = (const float*)d_in[6];
    const int*   map1_in  = (const int*)d_in[7];
    const int*   map1_out = (const int*)d_in[8];
    const int*   map2_in  = (const int*)d_in[9];
    const int*   map2_out = (const int*)d_in[10];
    float* out = (float*)d_out;

    void *accPtr, *xhiPtr, *xloPtr, *yhiPtr, *yloPtr, *whiPtr, *wloPtr;
    cudaGetSymbolAddress(&accPtr, g_acc);
    cudaGetSymbolAddress(&xhiPtr, g_xhi);
    cudaGetSymbolAddress(&xloPtr, g_xlo);
    cudaGetSymbolAddress(&yhiPtr, g_yhi);
    cudaGetSymbolAddress(&yloPtr, g_ylo);
    cudaGetSymbolAddress(&whiPtr, g_wthi);
    cudaGetSymbolAddress(&wloPtr, g_wtlo);

    const __nv_bfloat16* w1hi = (const __nv_bfloat16*)whiPtr;
    const __nv_bfloat16* w1lo = (const __nv_bfloat16*)wloPtr;
    const __nv_bfloat16* w2hi = (const __nv_bfloat16*)((const char*)whiPtr + WLAYER_B);
    const __nv_bfloat16* w2lo = (const __nv_bfloat16*)((const char*)wloPtr + WLAYER_B);

    cudaFuncSetAttribute(spconv_mma_kernel,
                         cudaFuncAttributeMaxDynamicSharedMemorySize, DYN_SMEM);

    const dim3 convGrid(M_MAP / BT, KNUM);
    const int  elem4   = (N_PTS * C) / 4;
    const int  ppGrid  = elem4 / 256;        // prepack_x: 1 float4/thread
    const int  apGrid  = elem4 / 2048;       // apply: 8 float4/thread

    // ---- prepack both layers' weights + x up front ----
    prepack_x_kernel<<<ppGrid, 256>>>(x, (__nv_bfloat16*)xhiPtr,
                                      (__nv_bfloat16*)xloPtr, (float*)accPtr);
    prepack_w_kernel<<<2 * KNUM, 256>>>(W1, W2);

    // ---- layer 1 (conv CTA(0,0) zeroes stats) ----
    spconv_mma_kernel<<<convGrid, 256, DYN_SMEM>>>(
        (const __nv_bfloat16*)xhiPtr, (const __nv_bfloat16*)xloPtr,
        w1hi, w1lo, map1_in, map1_out, (float*)accPtr);
    bn_stats_kernel<<<1024, 256>>>((const float*)accPtr);
    apply_bn_elu_split_kernel<<<apGrid, 256>>>(
        (float*)accPtr, gamma1, beta1,
        (__nv_bfloat16*)yhiPtr, (__nv_bfloat16*)yloPtr);

    // ---- layer 2 (conv CTA(0,0) zeroes stats AFTER apply read them) ----
    spconv_mma_kernel<<<convGrid, 256, DYN_SMEM>>>(
        (const __nv_bfloat16*)yhiPtr, (const __nv_bfloat16*)yloPtr,
        w2hi, w2lo, map2_in, map2_out, (float*)accPtr);
    bn_stats_kernel<<<1024, 256>>>((const float*)accPtr);
    apply_bn_res_elu_kernel<<<apGrid, 256>>>(
        (const float*)accPtr, gamma2, beta2, x, out);
}

// round 17
// speedup vs baseline: 1.1497x; 1.1497x over previous
#include <cuda_runtime.h>
#include <cuda_fp16.h>
#include <math.h>
#include <stdint.h>

#define N_PTS 131072
#define C 128
#define KNUM 27
#define M_MAP 65536
#define EPS 1e-5f

#define BT 128            // map rows per CTA tile
#define KC 32             // k-elems per chunk
#define NCHUNK (C / KC)   // 4
#define PB 80             // smem row pitch in BYTES (40 fp16) — LDSM conflict-free
#define ARR_SZ (BT * PB)  // 10240 B per operand array
#define A_STAGE ARR_SZ          // single A array (xh only) = 10240 B
#define B_STAGE (2 * ARR_SZ)    // wh+wl = 20480 B
#define BREG (3 * A_STAGE)      // B region starts after 3 A stages = 30720
#define DYN_SMEM (BREG + 2 * B_STAGE)   // 71680 B
#define WCHUNK_B ARR_SZ         // one weight chunk image = 10240 B
#define WLAYER_B ((size_t)KNUM * NCHUNK * WCHUNK_B)
#define WSCALE 16384.0f
#define WSCALE_INV 6.103515625e-05f   // 1/16384 (exact)

// ---- scratch (static device allocations; allowed) ----
__device__ __align__(16) float  g_acc[(size_t)N_PTS * C];
__device__ __align__(16) __half g_xh[(size_t)N_PTS * C];
__device__ __align__(16) __half g_yh[(size_t)N_PTS * C];
// weight smem-images for BOTH layers: [layer][k][chunk][row][40 fp16 @80B pitch]
__device__ __align__(16) __half g_wthi[2 * (size_t)KNUM * NCHUNK * BT * (PB / 2)];
__device__ __align__(16) __half g_wtlo[2 * (size_t)KNUM * NCHUNK * BT * (PB / 2)];
__device__ __align__(16) float g_sum[C];
__device__ __align__(16) float g_sq[C];

// ---------------------------------------------------------------------------
// helpers
// ---------------------------------------------------------------------------
__device__ __forceinline__ uint32_t smem_u32(const void* p)
{
    uint32_t a;
    asm("{ .reg .u64 t; cvta.to.shared.u64 t, %1; cvt.u32.u64 %0, t; }"
        : "=r"(a) : "l"(p));
    return a;
}

__device__ __forceinline__ void mma16816h(float* c, const unsigned* a,
                                          unsigned b0, unsigned b1)
{
    asm volatile(
        "mma.sync.aligned.m16n8k16.row.col.f32.f16.f16.f32 "
        "{%0,%1,%2,%3}, {%4,%5,%6,%7}, {%8,%9}, {%0,%1,%2,%3};"
        : "+f"(c[0]), "+f"(c[1]), "+f"(c[2]), "+f"(c[3])
        : "r"(a[0]), "r"(a[1]), "r"(a[2]), "r"(a[3]), "r"(b0), "r"(b1));
}

__device__ __forceinline__ void ldsm_x4(unsigned* r, uint32_t addr)
{
    asm volatile("ldmatrix.sync.aligned.m8n8.x4.shared.b16 {%0,%1,%2,%3}, [%4];"
                 : "=r"(r[0]), "=r"(r[1]), "=r"(r[2]), "=r"(r[3]) : "r"(addr));
}

#define CP_ASYNC16(dst, src) \
    asm volatile("cp.async.cg.shared.global [%0], [%1], 16;" :: "r"(dst), "l"(src))
#define CP_COMMIT() asm volatile("cp.async.commit_group;" ::: "memory")

__device__ __forceinline__ void bulk_copy(uint32_t dst, const void* src,
                                          uint32_t bytes, uint32_t mbar)
{
    asm volatile(
        "cp.async.bulk.shared::cta.global.mbarrier::complete_tx::bytes "
        "[%0], [%1], %2, [%3];"
        :: "r"(dst), "l"(src), "r"(bytes), "r"(mbar) : "memory");
}

__device__ __forceinline__ void mbar_expect_tx(uint32_t mbar, uint32_t bytes)
{
    asm volatile("mbarrier.arrive.expect_tx.shared.b64 _, [%0], %1;"
                 :: "r"(mbar), "r"(bytes) : "memory");
}

__device__ __forceinline__ void mbar_wait(uint32_t mbar, uint32_t parity)
{
    uint32_t done;
    asm volatile(
        "{\n\t.reg .pred p;\n\t"
        "mbarrier.try_wait.parity.acquire.cta.shared::cta.b64 p, [%1], %2;\n\t"
        "selp.b32 %0, 1, 0, p;\n\t}"
        : "=r"(done) : "r"(mbar), "r"(parity) : "memory");
    if (!done) {
        asm volatile(
            "{\n\t.reg .pred P1;\n\t"
            "WL_%=:\n\t"
            "mbarrier.try_wait.parity.acquire.cta.shared::cta.b64 P1, [%0], %1, 0x989680;\n\t"
            "@P1 bra.uni WD_%=;\n\t"
            "bra.uni WL_%=;\n\t"
            "WD_%=:\n\t}"
            :: "r"(mbar), "r"(parity) : "memory");
    }
}

__device__ __forceinline__ float elu_f(float x)
{
    return x > 0.0f ? x : expm1f(x);
}

// ---------------------------------------------------------------------------
// Prepack kernels
// ---------------------------------------------------------------------------
__global__ __launch_bounds__(256)
void prepack_x_kernel(const float* __restrict__ src,
                      __half* __restrict__ xh,
                      float* __restrict__ acc_zero)
{
    size_t i = (size_t)blockIdx.x * 256 + threadIdx.x;
    float4 v = ((const float4*)src)[i];
    __half2 h01 = __half2(__float2half_rn(v.x), __float2half_rn(v.y));
    __half2 h23 = __half2(__float2half_rn(v.z), __float2half_rn(v.w));
    ((__half2*)xh)[i * 2 + 0] = h01;
    ((__half2*)xh)[i * 2 + 1] = h23;
    ((float4*)acc_zero)[i] = make_float4(0.f, 0.f, 0.f, 0.f);   // layer-1 acc zero
}

// W[k][cin][n] fp32 * 2^14 -> split fp16 smem-image. Blocks 0..26: W1, 27..53: W2.
__global__ __launch_bounds__(256)
void prepack_w_kernel(const float* __restrict__ W1,
                      const float* __restrict__ W2)
{
    int b     = blockIdx.x;
    int layer = b >= KNUM ? 1 : 0;
    int k     = b - layer * KNUM;
    const float* Wk = (layer ? W2 : W1) + (size_t)k * C * C;
    __half* oh = g_wthi + (size_t)layer * KNUM * NCHUNK * BT * (PB / 2);
    __half* ol = g_wtlo + (size_t)layer * KNUM * NCHUNK * BT * (PB / 2);
    for (int idx = threadIdx.x; idx < C * C; idx += 256) {
        int n   = idx & (C - 1);
        int cin = idx >> 7;
        float v = Wk[(size_t)cin * C + n] * WSCALE;
        __half h = __float2half_rn(v);
        __half l = __float2half_rn(v - __half2float(h));
        int ch  = cin >> 5;
        int col = cin & 31;
        size_t off = ((size_t)(k * NCHUNK + ch) * BT + n) * (PB / 2) + col;
        oh[off] = h;
        ol[off] = l;
    }
}

// ---------------------------------------------------------------------------
// Sparse conv: fp16 2-term (xh*wh + xh*wl), weights prescaled by 2^14.
// CTA = 128 map rows x 128 out channels; 8 warps, warp tile 32M x 64N.
// A via 3-stage cp.async gather (single array); B via 2-stage bulk (2 arrays).
// ONE barrier per chunk. CTA(0,0) zeroes BN stats.
// ---------------------------------------------------------------------------
__global__ __launch_bounds__(256, 2)
void spconv_mma_kernel(const __half* __restrict__ xh,
                       const __half* __restrict__ wt_hi,
                       const __half* __restrict__ wt_lo,
                       const int* __restrict__ map_in,
                       const int* __restrict__ map_out,
                       float* __restrict__ acc_out)
{
    extern __shared__ __align__(16) char dynsmem[];
    __shared__ int rowidx[BT];
    __shared__ int outidx[BT];
    __shared__ __align__(8) uint64_t s_mbar[2];

    const int k    = blockIdx.y;
    const int m0   = blockIdx.x * BT;
    const int tid  = threadIdx.x;
    const int warp = tid >> 5;
    const int lane = tid & 31;
    const int wm   = warp & 3;            // M warp: 32 rows
    const int wn   = warp >> 2;           // N warp: 64 cols

    if (blockIdx.x == 0 && blockIdx.y == 0 && tid < C) {
        g_sum[tid] = 0.0f;
        g_sq[tid]  = 0.0f;
    }

    const int* mi = map_in  + (size_t)k * M_MAP + m0;
    const int* mo = map_out + (size_t)k * M_MAP + m0;
    const char* wbh = (const char*)wt_hi + (size_t)k * NCHUNK * WCHUNK_B;
    const char* wbl = (const char*)wt_lo + (size_t)k * NCHUNK * WCHUNK_B;

    const uint32_t sbase = smem_u32(dynsmem);
    const uint32_t mb0   = smem_u32(&s_mbar[0]);
    const uint32_t mb1   = smem_u32(&s_mbar[1]);

    if (tid < BT) {
        rowidx[tid] = mi[tid];
        outidx[tid] = mo[tid];
    }
    if (tid == 0) {
        asm volatile("mbarrier.init.shared.b64 [%0], 1;" :: "r"(mb0) : "memory");
        asm volatile("mbarrier.init.shared.b64 [%0], 1;" :: "r"(mb1) : "memory");
        asm volatile("fence.proxy.async.shared::cta;" ::: "memory");
    }
    __syncthreads();

    // --- per-thread cp.async source/dest for A (2 transfers per chunk) ---
    const __half* srcs[2];
    uint32_t doffs[2];
    #pragma unroll
    for (int it = 0; it < 2; it++) {
        int idx = tid + it * 256;          // 0..511
        int row = idx >> 2;                // 0..127
        int q   = idx & 3;                 // 16B granule
        srcs[it]  = xh + (size_t)rowidx[row] * C + q * 8;
        doffs[it] = (uint32_t)(row * PB + q * 16);
    }

    // --- ldmatrix per-thread offsets (within a stage) ---
    const int mat = lane >> 3;
    const int mi8 = lane & 7;
    const uint32_t aRow  = (uint32_t)(wm * 32 + (mat & 1) * 8 + mi8);
    const uint32_t aColB = (uint32_t)((mat >> 1) * 8) * 2;
    uint32_t aOff[2];
    aOff[0] = aRow * PB + aColB;
    aOff[1] = (aRow + 16) * PB + aColB;
    const uint32_t bRow  = (uint32_t)(wn * 64 + (mat >> 1) * 8 + mi8);
    const uint32_t bColB = (uint32_t)((mat & 1) * 8) * 2;
    uint32_t bOff[4];
    #pragma unroll
    for (int p = 0; p < 4; p++)
        bOff[p] = (bRow + p * 16) * PB + bColB;

    float acc[2][8][4];
    #pragma unroll
    for (int i = 0; i < 2; i++)
        #pragma unroll
        for (int j = 0; j < 8; j++)
            #pragma unroll
            for (int t = 0; t < 4; t++) acc[i][j][t] = 0.0f;

    // ---- preload: A chunks 0,1 (stages 0,1) and B chunk 0 (stage 0) ----
    #pragma unroll
    for (int pre = 0; pre < 2; pre++) {
        const uint32_t st = (uint32_t)(pre * A_STAGE);
        const int coff = pre * KC;
        #pragma unroll
        for (int it = 0; it < 2; it++)
            CP_ASYNC16(sbase + st + doffs[it], srcs[it] + coff);
        CP_COMMIT();
    }
    if (tid == 0) {
        mbar_expect_tx(mb0, 2 * WCHUNK_B);
        bulk_copy(sbase + BREG, wbh, WCHUNK_B, mb0);
        bulk_copy(sbase + BREG + ARR_SZ, wbl, WCHUNK_B, mb0);
    }

    #pragma unroll
    for (int ch = 0; ch < NCHUNK; ch++) {
        // ---- wait for chunk ch (A groups FIFO; B via mbarrier) ----
        if (ch < NCHUNK - 1) asm volatile("cp.async.wait_group 1;" ::: "memory");
        else                 asm volatile("cp.async.wait_group 0;" ::: "memory");
        mbar_wait((ch & 1) ? mb1 : mb0, (uint32_t)((ch >> 1) & 1));
        __syncthreads();   // ONLY barrier this chunk

        // ---- issue next-chunk copies (safe: stage readers all past barrier) ----
        if (ch + 2 < NCHUNK) {
            const uint32_t st = (uint32_t)(((ch + 2) % 3) * A_STAGE);
            const int coff = (ch + 2) * KC;
            #pragma unroll
            for (int it = 0; it < 2; it++)
                CP_ASYNC16(sbase + st + doffs[it], srcs[it] + coff);
            CP_COMMIT();
        }
        if (ch + 1 < NCHUNK && tid == 0) {
            const uint32_t nmb = ((ch + 1) & 1) ? mb1 : mb0;
            const uint32_t dst = sbase + BREG + (uint32_t)(((ch + 1) & 1) * B_STAGE);
            mbar_expect_tx(nmb, 2 * WCHUNK_B);
            bulk_copy(dst, wbh + (size_t)(ch + 1) * WCHUNK_B, WCHUNK_B, nmb);
            bulk_copy(dst + ARR_SZ, wbl + (size_t)(ch + 1) * WCHUNK_B, WCHUNK_B, nmb);
        }

        const uint32_t stA = sbase + (uint32_t)((ch % 3) * A_STAGE);
        const uint32_t stB = sbase + BREG + (uint32_t)((ch % 2) * B_STAGE);

        #pragma unroll
        for (int ks = 0; ks < KC / 16; ks++) {
            const uint32_t kb = (uint32_t)(ks * 32);
            unsigned ah[2][4];
            ldsm_x4(ah[0], stA + aOff[0] + kb);
            ldsm_x4(ah[1], stA + aOff[1] + kb);
            #pragma unroll
            for (int p = 0; p < 4; p++) {
                unsigned bh[4], bl[4];
                ldsm_x4(bh, stB + bOff[p] + kb);
                ldsm_x4(bl, stB + ARR_SZ + bOff[p] + kb);
                #pragma unroll
                for (int ns = 0; ns < 2; ns++) {
                    const int nb = p * 2 + ns;
                    #pragma unroll
                    for (int mb = 0; mb < 2; mb++) {
                        mma16816h(acc[mb][nb], ah[mb], bh[ns * 2], bh[ns * 2 + 1]);
                        mma16816h(acc[mb][nb], ah[mb], bl[ns * 2], bl[ns * 2 + 1]);
                    }
                }
            }
        }
    }

    // ---- epilogue: undo 2^14 weight scale, shfl-swap, scatter v4 reds ----
    {
        const int g    = lane >> 2;
        const int tig  = lane & 3;
        const int oddp = tig & 1;
        #pragma unroll
        for (int mb = 0; mb < 2; mb++) {
            const int r    = wm * 32 + mb * 16 + g + oddp * 8;
            const int orow = outidx[r];
            float* dst = acc_out + (size_t)orow * C + wn * 64 + (tig >> 1) * 4;
            #pragma unroll
            for (int nb = 0; nb < 8; nb++) {
                float s0 = oddp ? acc[mb][nb][0] : acc[mb][nb][2];
                float s1 = oddp ? acc[mb][nb][1] : acc[mb][nb][3];
                float r0 = __shfl_xor_sync(0xFFFFFFFFu, s0, 1);
                float r1 = __shfl_xor_sync(0xFFFFFFFFu, s1, 1);
                float v0 = (oddp ? r0 : acc[mb][nb][0]) * WSCALE_INV;
                float v1 = (oddp ? r1 : acc[mb][nb][1]) * WSCALE_INV;
                float v2 = (oddp ? acc[mb][nb][2] : r0) * WSCALE_INV;
                float v3 = (oddp ? acc[mb][nb][3] : r1) * WSCALE_INV;
                asm volatile("red.global.v4.f32.add [%0], {%1, %2, %3, %4};"
                             :: "l"(dst + nb * 8), "f"(v0), "f"(v1), "f"(v2), "f"(v3)
                             : "memory");
            }
        }
    }
}

// ---------------------------------------------------------------------------
// BN stats (4-way unrolled)
// ---------------------------------------------------------------------------
__global__ __launch_bounds__(256)
void bn_stats_kernel(const float* __restrict__ a)
{
    __shared__ float4 ss[256];
    __shared__ float4 qq[256];
    const int tid = threadIdx.x;
    const int c4  = tid & 31;
    const int ro  = tid >> 5;

    float4 s = make_float4(0.f, 0.f, 0.f, 0.f);
    float4 p = make_float4(0.f, 0.f, 0.f, 0.f);
    for (int r = blockIdx.x * 32 + ro; r < N_PTS; r += gridDim.x * 32) {
        float4 v0 = ((const float4*)a)[(size_t)r * 32 + c4];
        float4 v1 = ((const float4*)a)[(size_t)(r + 8) * 32 + c4];
        float4 v2 = ((const float4*)a)[(size_t)(r + 16) * 32 + c4];
        float4 v3 = ((const float4*)a)[(size_t)(r + 24) * 32 + c4];
        s.x += (v0.x + v1.x) + (v2.x + v3.x);
        s.y += (v0.y + v1.y) + (v2.y + v3.y);
        s.z += (v0.z + v1.z) + (v2.z + v3.z);
        s.w += (v0.w + v1.w) + (v2.w + v3.w);
        p.x += (v0.x * v0.x + v1.x * v1.x) + (v2.x * v2.x + v3.x * v3.x);
        p.y += (v0.y * v0.y + v1.y * v1.y) + (v2.y * v2.y + v3.y * v3.y);
        p.z += (v0.z * v0.z + v1.z * v1.z) + (v2.z * v2.z + v3.z * v3.z);
        p.w += (v0.w * v0.w + v1.w * v1.w) + (v2.w * v2.w + v3.w * v3.w);
    }
    ss[tid] = s;
    qq[tid] = p;
    __syncthreads();
    if (tid < 32) {
        float4 S = ss[tid], Q = qq[tid];
        #pragma unroll
        for (int j = 1; j < 8; j++) {
            float4 s2 = ss[tid + j * 32], q2 = qq[tid + j * 32];
            S.x += s2.x; S.y += s2.y; S.z += s2.z; S.w += s2.w;
            Q.x += q2.x; Q.y += q2.y; Q.z += q2.z; Q.w += q2.w;
        }
        atomicAdd(&g_sum[tid * 4 + 0], S.x);
        atomicAdd(&g_sum[tid * 4 + 1], S.y);
        atomicAdd(&g_sum[tid * 4 + 2], S.z);
        atomicAdd(&g_sum[tid * 4 + 3], S.w);
        atomicAdd(&g_sq[tid * 4 + 0], Q.x);
        atomicAdd(&g_sq[tid * 4 + 1], Q.y);
        atomicAdd(&g_sq[tid * 4 + 2], Q.z);
        atomicAdd(&g_sq[tid * 4 + 3], Q.w);
    }
}

// ---------------------------------------------------------------------------
// Apply kernels: finalize folded in, 8 float4s per thread
// ---------------------------------------------------------------------------
__global__ __launch_bounds__(256)
void apply_bn_elu_half_kernel(float* __restrict__ a,
                              const float* __restrict__ gamma,
                              const float* __restrict__ beta,
                              __half* __restrict__ yh)
{
    __shared__ float s_scale[C];
    __shared__ float s_shift[C];
    const int tid = threadIdx.x;
    if (tid < C) {
        float m  = g_sum[tid] * (1.0f / N_PTS);
        float v  = g_sq[tid] * (1.0f / N_PTS) - m * m;
        float is = rsqrtf(v + EPS);
        float sc = is * gamma[tid];
        s_scale[tid] = sc;
        s_shift[tid] = beta[tid] - m * sc;
    }
    __syncthreads();
    const int c4 = tid & 31;
    float4 sc = ((const float4*)s_scale)[c4];
    float4 sh = ((const float4*)s_shift)[c4];
    #pragma unroll
    for (int it = 0; it < 8; it++) {
        size_t idx = (size_t)blockIdx.x * 2048 + it * 256 + tid;
        float4 v = ((const float4*)a)[idx];
        ((float4*)a)[idx] = make_float4(0.f, 0.f, 0.f, 0.f);   // zero acc for L2
        float4 r;
        r.x = elu_f(fmaf(v.x, sc.x, sh.x));
        r.y = elu_f(fmaf(v.y, sc.y, sh.y));
        r.z = elu_f(fmaf(v.z, sc.z, sh.z));
        r.w = elu_f(fmaf(v.w, sc.w, sh.w));
        ((__half2*)yh)[idx * 2 + 0] = __half2(__float2half_rn(r.x), __float2half_rn(r.y));
        ((__half2*)yh)[idx * 2 + 1] = __half2(__float2half_rn(r.z), __float2half_rn(r.w));
    }
}

__global__ __launch_bounds__(256)
void apply_bn_res_elu_kernel(const float* __restrict__ a,
                             const float* __restrict__ gamma,
                             const float* __restrict__ beta,
                             const float* __restrict__ resid,
                             float* __restrict__ o)
{
    __shared__ float s_scale[C];
    __shared__ float s_shift[C];
    const int tid = threadIdx.x;
    if (tid < C) {
        float m  = g_sum[tid] * (1.0f / N_PTS);
        float v  = g_sq[tid] * (1.0f / N_PTS) - m * m;
        float is = rsqrtf(v + EPS);
        float sc = is * gamma[tid];
        s_scale[tid] = sc;
        s_shift[tid] = beta[tid] - m * sc;
    }
    __syncthreads();
    const int c4 = tid & 31;
    float4 sc = ((const float4*)s_scale)[c4];
    float4 sh = ((const float4*)s_shift)[c4];
    #pragma unroll
    for (int it = 0; it < 8; it++) {
        size_t idx = (size_t)blockIdx.x * 2048 + it * 256 + tid;
        float4 v  = ((const float4*)a)[idx];
        float4 rs = ((const float4*)resid)[idx];
        float4 r;
        r.x = elu_f(fmaf(v.x, sc.x, sh.x) + rs.x);
        r.y = elu_f(fmaf(v.y, sc.y, sh.y) + rs.y);
        r.z = elu_f(fmaf(v.z, sc.z, sh.z) + rs.z);
        r.w = elu_f(fmaf(v.w, sc.w, sh.w) + rs.w);
        ((float4*)o)[idx] = r;
    }
}

// ---------------------------------------------------------------------------
// Launch
// ---------------------------------------------------------------------------
extern "C" void kernel_launch(void* const* d_in, const int* in_sizes, int n_in,
                              void* d_out, int out_size)
{
    const float* x       = (const float*)d_in[0];
    const float* W1      = (const float*)d_in[1];
    const float* gamma1  = (const float*)d_in[2];
    const float* beta1   = (const float*)d_in[3];
    const float* W2      = (const float*)d_in[4];
    const float* gamma2  = (const float*)d_in[5];
    const float* beta2   = (const float*)d_in[6];
    const int*   map1_in  = (const int*)d_in[7];
    const int*   map1_out = (const int*)d_in[8];
    const int*   map2_in  = (const int*)d_in[9];
    const int*   map2_out = (const int*)d_in[10];
    float* out = (float*)d_out;

    void *accPtr, *xhPtr, *yhPtr, *whiPtr, *wloPtr;
    cudaGetSymbolAddress(&accPtr, g_acc);
    cudaGetSymbolAddress(&xhPtr, g_xh);
    cudaGetSymbolAddress(&yhPtr, g_yh);
    cudaGetSymbolAddress(&whiPtr, g_wthi);
    cudaGetSymbolAddress(&wloPtr, g_wtlo);

    const __half* w1hi = (const __half*)whiPtr;
    const __half* w1lo = (const __half*)wloPtr;
    const __half* w2hi = (const __half*)((const char*)whiPtr + WLAYER_B);
    const __half* w2lo = (const __half*)((const char*)wloPtr + WLAYER_B);

    cudaFuncSetAttribute(spconv_mma_kernel,
                         cudaFuncAttributeMaxDynamicSharedMemorySize, DYN_SMEM);

    const dim3 convGrid(M_MAP / BT, KNUM);
    const int  elem4   = (N_PTS * C) / 4;
    const int  ppGrid  = elem4 / 256;
    const int  apGrid  = elem4 / 2048;

    // ---- prepack both layers' weights + x up front ----
    prepack_x_kernel<<<ppGrid, 256>>>(x, (__half*)xhPtr, (float*)accPtr);
    prepack_w_kernel<<<2 * KNUM, 256>>>(W1, W2);

    // ---- layer 1 (conv CTA(0,0) zeroes stats) ----
    spconv_mma_kernel<<<convGrid, 256, DYN_SMEM>>>(
        (const __half*)xhPtr, w1hi, w1lo, map1_in, map1_out, (float*)accPtr);
    bn_stats_kernel<<<1024, 256>>>((const float*)accPtr);
    apply_bn_elu_half_kernel<<<apGrid, 256>>>(
        (float*)accPtr, gamma1, beta1, (__half*)yhPtr);

    // ---- layer 2 (conv CTA(0,0) zeroes stats AFTER apply read them) ----
    spconv_mma_kernel<<<convGrid, 256, DYN_SMEM>>>(
        (const __half*)yhPtr, w2hi, w2lo, map2_in, map2_out, (float*)accPtr);
    bn_stats_kernel<<<1024, 256>>>((const float*)accPtr);
    apply_bn_res_elu_kernel<<<apGrid, 256>>>(
        (const float*)accPtr, gamma2, beta2, x, out);
}